// round 8
// baseline (speedup 1.0000x reference)
#include <cuda_runtime.h>
#include <cuda_bf16.h>
#include <stdint.h>

// out[r,o] = tanh(scale(r) * dot(enc_row(r), W[o,:]) + b[o])
//   r = b*128 + m (m = l*4+n, l<32) -> M=4096 ; enc phys row = b*2048 + m
//   K=256, N=256. (Spectral DCT/mask/IDCT collapses to mask*enc since the
//   band mask is independent of the DCT index.)
//
// Split-bf16 GEMM on mma.sync m16n8k16: x = hi + lo (both bf16);
// D = AhBh + AhBl + AlBh, fp32 accum (~5e-6 rel err).
//
// Round 8: 2 CTAs/SM with CORRECT smem budget. Per CTA: M=64, N=32, K=256,
// smem = (64+32)*1024 = 96KB: Ah/Al 32KB each, Bh/Bl 16KB each (B = 32 rows
// x 512B -> fits; round-7 crashed because N=64 B overflowed these regions).
// 256 threads = 8 warps = 4(M)x2(N), warp tile 16x16 (4 ldmatrix.x4 +
// 6 HMMA per k16). Grid (64,8) = 512 CTAs, 296 resident.

#define THREADS 256
#define OFF_AH 0
#define OFF_AL 32768
#define OFF_BH 65536
#define OFF_BL 81920
#define DYN_SMEM 98304

static __device__ __forceinline__ uint32_t smem_u32(const void* p) {
    uint32_t a;
    asm("{ .reg .u64 t; cvta.to.shared.u64 t, %1; cvt.u32.u64 %0, t; }"
        : "=r"(a) : "l"(p));
    return a;
}

static __device__ __forceinline__ void split2(float x, float y,
                                              uint32_t& hi, uint32_t& lo) {
    __nv_bfloat162 H = __floats2bfloat162_rn(x, y);
    float rx = x - __bfloat162float(H.x);
    float ry = y - __bfloat162float(H.y);
    __nv_bfloat162 L = __floats2bfloat162_rn(rx, ry);
    hi = *reinterpret_cast<uint32_t*>(&H);
    lo = *reinterpret_cast<uint32_t*>(&L);
}

static __device__ __forceinline__ void ldmx4(uint32_t* r, uint32_t addr) {
    asm volatile("ldmatrix.sync.aligned.m8n8.x4.shared.b16 {%0,%1,%2,%3}, [%4];"
                 : "=r"(r[0]), "=r"(r[1]), "=r"(r[2]), "=r"(r[3]) : "r"(addr));
}

static __device__ __forceinline__ void mma16816(float* c, const uint32_t* a,
                                                uint32_t b0, uint32_t b1) {
    asm volatile(
        "mma.sync.aligned.m16n8k16.row.col.f32.bf16.bf16.f32 "
        "{%0,%1,%2,%3},{%4,%5,%6,%7},{%8,%9},{%0,%1,%2,%3};"
        : "+f"(c[0]), "+f"(c[1]), "+f"(c[2]), "+f"(c[3])
        : "r"(a[0]), "r"(a[1]), "r"(a[2]), "r"(a[3]), "r"(b0), "r"(b1));
}

static __device__ __forceinline__ float tanh_fast(float x) {
    float e = __expf(2.0f * x);
    return 1.0f - __fdividef(2.0f, e + 1.0f);
}

__global__ __launch_bounds__(THREADS, 2) void spectral_hmma_kernel(
    const float* __restrict__ enc,
    const float* __restrict__ W,
    const float* __restrict__ bias,
    float* __restrict__ out)
{
    extern __shared__ __align__(16) uint8_t dyn[];
    const uint32_t sbase = smem_u32(dyn);

    const int tid = threadIdx.x;
    const int wid = tid >> 5;
    const int lid = tid & 31;
    const int bx = blockIdx.x;        // M tile, 0..63 (64 rows each)
    const int by = blockIdx.y;        // N tile, 0..7 (32 cols each)
    const int b    = bx >> 1;         // batch
    const int moff = (bx & 1) * 64;   // row offset within batch's 128 rows

    // ---- load + split A: 64 rows x 256 f32 -> Ah/Al bf16 (swizzled)
    #pragma unroll
    for (int it = 0; it < 8; ++it) {
        const int g   = tid + it * 256;      // chunk id, 0..2047
        const int row = g >> 5;              // 0..63
        const int ck  = g & 31;              // 16B chunk within row
        const float4* src = (const float4*)enc
            + ((size_t)(b * 2048 + moff + row)) * 64 + ck * 2;
        float4 v0 = src[0], v1 = src[1];
        uint4 h, l;
        split2(v0.x, v0.y, h.x, l.x);
        split2(v0.z, v0.w, h.y, l.y);
        split2(v1.x, v1.y, h.z, l.z);
        split2(v1.z, v1.w, h.w, l.w);
        uint32_t sw = row * 512 + (((ck ^ (row & 7)) & 31) << 4);
        *(uint4*)(dyn + OFF_AH + sw) = h;
        *(uint4*)(dyn + OFF_AL + sw) = l;
    }
    // ---- load + split B: W rows by*32..+31 (32 rows -> fits 16KB regions)
    #pragma unroll
    for (int it = 0; it < 4; ++it) {
        const int g   = tid + it * 256;      // 0..1023
        const int row = g >> 5;              // 0..31
        const int ck  = g & 31;
        const float4* src =
            (const float4*)W + ((size_t)(by * 32 + row)) * 64 + ck * 2;
        float4 v0 = src[0], v1 = src[1];
        uint4 h, l;
        split2(v0.x, v0.y, h.x, l.x);
        split2(v0.z, v0.w, h.y, l.y);
        split2(v1.x, v1.y, h.z, l.z);
        split2(v1.z, v1.w, h.w, l.w);
        uint32_t sw = row * 512 + (((ck ^ (row & 7)) & 31) << 4);
        *(uint4*)(dyn + OFF_BH + sw) = h;
        *(uint4*)(dyn + OFF_BL + sw) = l;
    }
    __syncthreads();

    // ---- warp tiling: 8 warps = 4(M, 16 rows) x 2(N, 16 cols)
    const int wm = wid & 3;
    const int wn = wid >> 2;
    const int rl = lid & 15;
    const int kadd = lid >> 4;

    const int aRow = wm * 16 + rl;
    const uint32_t aRowOff = aRow * 512;
    const int axor = aRow & 7;
    const int bRow = wn * 16 + rl;
    const uint32_t bRowOff = bRow * 512;
    const int bxor = bRow & 7;

    float acc[2][4];
    #pragma unroll
    for (int j = 0; j < 2; ++j)
        #pragma unroll
        for (int q = 0; q < 4; ++q)
            acc[j][q] = 0.f;

    // ---- fused mainloop: 4 ldmatrix.x4 + 6 HMMA per k16
    #pragma unroll 4
    for (int k16 = 0; k16 < 16; ++k16) {
        const int ch = k16 * 2 + kadd;
        const uint32_t aoff = aRowOff + (((ch ^ axor) & 31) << 4);
        const uint32_t boff = bRowOff + (((ch ^ bxor) & 31) << 4);
        uint32_t ah[4], al[4], bh[4], bl[4];
        ldmx4(ah, sbase + OFF_AH + aoff);
        ldmx4(al, sbase + OFF_AL + aoff);
        ldmx4(bh, sbase + OFF_BH + boff);
        ldmx4(bl, sbase + OFF_BL + boff);
        mma16816(acc[0], ah, bh[0], bh[2]);
        mma16816(acc[1], ah, bh[1], bh[3]);
        mma16816(acc[0], ah, bl[0], bl[2]);
        mma16816(acc[1], ah, bl[1], bl[3]);
        mma16816(acc[0], al, bh[0], bh[2]);
        mma16816(acc[1], al, bh[1], bh[3]);
    }

    // ---- epilogue: band scale, bias, tanh, store
    const int qr = lid >> 2;
    const int qc = (lid & 3) * 2;
    #pragma unroll
    for (int h = 0; h < 2; ++h) {
        const int m = wm * 16 + qr + h * 8;      // 0..63 (local)
        const int mfull = moff + m;              // 0..127 (within batch)
        const int n = mfull & 3, ls = mfull >> 2;
        const float scale = (n == 0) ? 1.0f
                          : (n == 1) ? ((ls < 16) ? 0.1f : 1.0f)
                          : 0.1f;
        float* orow = out + ((size_t)(bx * 64 + m)) * 256
                          + by * 32 + wn * 16 + qc;
        const float* brow = bias + by * 32 + wn * 16 + qc;
        #pragma unroll
        for (int nt = 0; nt < 2; ++nt) {
            float2 bb = *(const float2*)(brow + nt * 8);
            float2 o;
            o.x = tanh_fast(fmaf(scale, acc[nt][h * 2 + 0], bb.x));
            o.y = tanh_fast(fmaf(scale, acc[nt][h * 2 + 1], bb.y));
            *(float2*)(orow + nt * 8) = o;
        }
    }
}

extern "C" void kernel_launch(void* const* d_in, const int* in_sizes, int n_in,
                              void* d_out, int out_size) {
    const float* enc  = (const float*)d_in[0];
    const float* W    = (const float*)d_in[1];
    const float* bias = (const float*)d_in[2];
    float* out = (float*)d_out;

    cudaFuncSetAttribute(spectral_hmma_kernel,
                         cudaFuncAttributeMaxDynamicSharedMemorySize, DYN_SMEM);
    dim3 grid(64, 8);
    spectral_hmma_kernel<<<grid, THREADS, DYN_SMEM>>>(enc, W, bias, out);
}

// round 9
// speedup vs baseline: 1.3113x; 1.3113x over previous
#include <cuda_runtime.h>
#include <cuda_bf16.h>
#include <stdint.h>

// out[r,o] = tanh(scale(r) * dot(enc_row(r), W[o,:]) + b[o])
//   r = b*128 + m (m = l*4+n, l<32) -> M=4096 ; enc phys row = b*2048 + m
//   K=256, N=256. (Spectral DCT/mask/IDCT collapses to mask*enc since the
//   band mask is independent of the DCT index.)
//
// Split-bf16 GEMM on mma.sync m16n8k16: x = hi + lo (both bf16);
// D = AhBh + AhBl + AlBh, fp32 accum (~5e-6 rel err).
//
// Round 9: back to R6's winning tiling (M=128, N=64, K=256 per CTA, 192KB
// smem, grid (32,4)=128 CTAs = 1 wave) but 1024 threads = 32 warps/SM
// (R8's 2-small-CTA split kept warps/SM at 16 and doubled redundant loads
// -> regression). Warp grid 8(M)x4(N), tile 16x16: 4 ldmatrix.x4 + 6 HMMA
// per k16. Same total HMMA; double the latency hiding everywhere.

#define THREADS 1024
#define OFF_AH 0
#define OFF_AL 65536
#define OFF_BH 131072
#define OFF_BL 163840
#define DYN_SMEM 196608

static __device__ __forceinline__ uint32_t smem_u32(const void* p) {
    uint32_t a;
    asm("{ .reg .u64 t; cvta.to.shared.u64 t, %1; cvt.u32.u64 %0, t; }"
        : "=r"(a) : "l"(p));
    return a;
}

static __device__ __forceinline__ void split2(float x, float y,
                                              uint32_t& hi, uint32_t& lo) {
    __nv_bfloat162 H = __floats2bfloat162_rn(x, y);
    float rx = x - __bfloat162float(H.x);
    float ry = y - __bfloat162float(H.y);
    __nv_bfloat162 L = __floats2bfloat162_rn(rx, ry);
    hi = *reinterpret_cast<uint32_t*>(&H);
    lo = *reinterpret_cast<uint32_t*>(&L);
}

static __device__ __forceinline__ void ldmx4(uint32_t* r, uint32_t addr) {
    asm volatile("ldmatrix.sync.aligned.m8n8.x4.shared.b16 {%0,%1,%2,%3}, [%4];"
                 : "=r"(r[0]), "=r"(r[1]), "=r"(r[2]), "=r"(r[3]) : "r"(addr));
}

static __device__ __forceinline__ void mma16816(float* c, const uint32_t* a,
                                                uint32_t b0, uint32_t b1) {
    asm volatile(
        "mma.sync.aligned.m16n8k16.row.col.f32.bf16.bf16.f32 "
        "{%0,%1,%2,%3},{%4,%5,%6,%7},{%8,%9},{%0,%1,%2,%3};"
        : "+f"(c[0]), "+f"(c[1]), "+f"(c[2]), "+f"(c[3])
        : "r"(a[0]), "r"(a[1]), "r"(a[2]), "r"(a[3]), "r"(b0), "r"(b1));
}

static __device__ __forceinline__ float tanh_fast(float x) {
    float e = __expf(2.0f * x);
    return 1.0f - __fdividef(2.0f, e + 1.0f);
}

__global__ __launch_bounds__(THREADS, 1) void spectral_hmma_kernel(
    const float* __restrict__ enc,
    const float* __restrict__ W,
    const float* __restrict__ bias,
    float* __restrict__ out)
{
    extern __shared__ __align__(16) uint8_t dyn[];
    const uint32_t sbase = smem_u32(dyn);

    const int tid = threadIdx.x;
    const int wid = tid >> 5;
    const int lid = tid & 31;
    const int bx = blockIdx.x;   // batch (M tile), 0..31
    const int by = blockIdx.y;   // N tile, 0..3

    // ---- load + split A: 128 rows x 256 f32 -> Ah/Al bf16 (swizzled)
    #pragma unroll
    for (int it = 0; it < 4; ++it) {
        const int g   = tid + it * 1024;     // chunk id, 0..4095
        const int row = g >> 5;              // 0..127
        const int ck  = g & 31;              // 16B chunk within row
        const float4* src =
            (const float4*)enc + ((size_t)(bx * 2048 + row)) * 64 + ck * 2;
        float4 v0 = src[0], v1 = src[1];
        uint4 h, l;
        split2(v0.x, v0.y, h.x, l.x);
        split2(v0.z, v0.w, h.y, l.y);
        split2(v1.x, v1.y, h.z, l.z);
        split2(v1.z, v1.w, h.w, l.w);
        uint32_t sw = row * 512 + (((ck ^ (row & 7)) & 31) << 4);
        *(uint4*)(dyn + OFF_AH + sw) = h;
        *(uint4*)(dyn + OFF_AL + sw) = l;
    }
    // ---- load + split B: W rows by*64..+63
    #pragma unroll
    for (int it = 0; it < 2; ++it) {
        const int g   = tid + it * 1024;     // 0..2047
        const int row = g >> 5;              // 0..63
        const int ck  = g & 31;
        const float4* src =
            (const float4*)W + ((size_t)(by * 64 + row)) * 64 + ck * 2;
        float4 v0 = src[0], v1 = src[1];
        uint4 h, l;
        split2(v0.x, v0.y, h.x, l.x);
        split2(v0.z, v0.w, h.y, l.y);
        split2(v1.x, v1.y, h.z, l.z);
        split2(v1.z, v1.w, h.w, l.w);
        uint32_t sw = row * 512 + (((ck ^ (row & 7)) & 31) << 4);
        *(uint4*)(dyn + OFF_BH + sw) = h;
        *(uint4*)(dyn + OFF_BL + sw) = l;
    }
    __syncthreads();

    // ---- warp tiling: 32 warps = 8(M, 16 rows) x 4(N, 16 cols)
    const int wm = wid & 7;
    const int wn = wid >> 3;
    const int rl = lid & 15;
    const int kadd = lid >> 4;

    const int aRow = wm * 16 + rl;
    const uint32_t aRowOff = aRow * 512;
    const int axor = aRow & 7;
    const int bRow = wn * 16 + rl;
    const uint32_t bRowOff = bRow * 512;
    const int bxor = bRow & 7;

    float acc[2][4];
    #pragma unroll
    for (int j = 0; j < 2; ++j)
        #pragma unroll
        for (int q = 0; q < 4; ++q)
            acc[j][q] = 0.f;

    // ---- fused mainloop: 4 ldmatrix.x4 + 6 HMMA per k16
    #pragma unroll 4
    for (int k16 = 0; k16 < 16; ++k16) {
        const int ch = k16 * 2 + kadd;
        const uint32_t aoff = aRowOff + (((ch ^ axor) & 31) << 4);
        const uint32_t boff = bRowOff + (((ch ^ bxor) & 31) << 4);
        uint32_t ah[4], al[4], bh[4], bl[4];
        ldmx4(ah, sbase + OFF_AH + aoff);
        ldmx4(al, sbase + OFF_AL + aoff);
        ldmx4(bh, sbase + OFF_BH + boff);
        ldmx4(bl, sbase + OFF_BL + boff);
        mma16816(acc[0], ah, bh[0], bh[2]);
        mma16816(acc[1], ah, bh[1], bh[3]);
        mma16816(acc[0], ah, bl[0], bl[2]);
        mma16816(acc[1], ah, bl[1], bl[3]);
        mma16816(acc[0], al, bh[0], bh[2]);
        mma16816(acc[1], al, bh[1], bh[3]);
    }

    // ---- epilogue: band scale, bias, tanh, store
    const int qr = lid >> 2;
    const int qc = (lid & 3) * 2;
    #pragma unroll
    for (int h = 0; h < 2; ++h) {
        const int m = wm * 16 + qr + h * 8;      // 0..127
        const int n = m & 3, ls = m >> 2;
        const float scale = (n == 0) ? 1.0f
                          : (n == 1) ? ((ls < 16) ? 0.1f : 1.0f)
                          : 0.1f;
        float* orow = out + ((size_t)(bx * 128 + m)) * 256
                          + by * 64 + wn * 16 + qc;
        const float* brow = bias + by * 64 + wn * 16 + qc;
        #pragma unroll
        for (int nt = 0; nt < 2; ++nt) {
            float2 bb = *(const float2*)(brow + nt * 8);
            float2 o;
            o.x = tanh_fast(fmaf(scale, acc[nt][h * 2 + 0], bb.x));
            o.y = tanh_fast(fmaf(scale, acc[nt][h * 2 + 1], bb.y));
            *(float2*)(orow + nt * 8) = o;
        }
    }
}

extern "C" void kernel_launch(void* const* d_in, const int* in_sizes, int n_in,
                              void* d_out, int out_size) {
    const float* enc  = (const float*)d_in[0];
    const float* W    = (const float*)d_in[1];
    const float* bias = (const float*)d_in[2];
    float* out = (float*)d_out;

    cudaFuncSetAttribute(spectral_hmma_kernel,
                         cudaFuncAttributeMaxDynamicSharedMemorySize, DYN_SMEM);
    dim3 grid(32, 4);
    spectral_hmma_kernel<<<grid, THREADS, DYN_SMEM>>>(enc, W, bias, out);
}

// round 10
// speedup vs baseline: 1.3145x; 1.0025x over previous
#include <cuda_runtime.h>
#include <cuda_fp16.h>
#include <stdint.h>

// out[r,o] = tanh(scale(r) * dot(enc_row(r), W[o,:]) + b[o])
//   r = b*128 + m (m = l*4+n, l<32) -> M=4096 ; enc phys row = b*2048 + m
//   K=256, N=256. (Spectral DCT/mask/IDCT collapses to mask*enc since the
//   band mask is independent of the DCT index.)
//
// fp16 HMMA (m16n8k16 f16, fp32 accum): A stored as SINGLE fp16 (err 2^-12),
// B split hi+lo fp16: D = A*Bh + A*Bl -> rel err ~2.4e-4 < 1e-3.
//
// Round 10: per CTA M=128 (one batch), N=32, K=256; smem = A 64KB + Bh 16KB
// + Bl 16KB = 96KB -> 2 CTAs/SM (phase overlap), grid (32,8)=256 CTAs = 1
// wave. 512 threads = 16 warps: 4(M:32 rows) x 2(N:16 cols) x 2(K-split:128)
// with smem reduction of the 2 K-partials. LDSM/SM ~512KB (half of R9).

#define THREADS 512
#define OFF_A  0
#define OFF_BH 65536
#define OFF_BL 81920
#define DYN_SMEM 98304

static __device__ __forceinline__ uint32_t smem_u32(const void* p) {
    uint32_t a;
    asm("{ .reg .u64 t; cvta.to.shared.u64 t, %1; cvt.u32.u64 %0, t; }"
        : "=r"(a) : "l"(p));
    return a;
}

static __device__ __forceinline__ void ldmx4(uint32_t* r, uint32_t addr) {
    asm volatile("ldmatrix.sync.aligned.m8n8.x4.shared.b16 {%0,%1,%2,%3}, [%4];"
                 : "=r"(r[0]), "=r"(r[1]), "=r"(r[2]), "=r"(r[3]) : "r"(addr));
}

static __device__ __forceinline__ void mma16816(float* c, const uint32_t* a,
                                                uint32_t b0, uint32_t b1) {
    asm volatile(
        "mma.sync.aligned.m16n8k16.row.col.f32.f16.f16.f32 "
        "{%0,%1,%2,%3},{%4,%5,%6,%7},{%8,%9},{%0,%1,%2,%3};"
        : "+f"(c[0]), "+f"(c[1]), "+f"(c[2]), "+f"(c[3])
        : "r"(a[0]), "r"(a[1]), "r"(a[2]), "r"(a[3]), "r"(b0), "r"(b1));
}

static __device__ __forceinline__ float tanh_fast(float x) {
    float e = __expf(2.0f * x);
    return 1.0f - __fdividef(2.0f, e + 1.0f);
}

__global__ __launch_bounds__(THREADS, 2) void spectral_hmma_kernel(
    const float* __restrict__ enc,
    const float* __restrict__ W,
    const float* __restrict__ bias,
    float* __restrict__ out)
{
    extern __shared__ __align__(16) uint8_t dyn[];
    const uint32_t sbase = smem_u32(dyn);

    const int tid = threadIdx.x;
    const int wid = tid >> 5;
    const int lid = tid & 31;
    const int bx = blockIdx.x;   // batch (M=128 rows), 0..31
    const int by = blockIdx.y;   // N tile (32 cols), 0..7

    // ---- load A: 128 rows x 256 f32 -> single fp16 (swizzled, 512B rows)
    #pragma unroll
    for (int it = 0; it < 8; ++it) {
        const int g   = tid + it * 512;      // chunk id, 0..4095
        const int row = g >> 5;              // 0..127
        const int ck  = g & 31;              // 16B chunk (8 f16) within row
        const float4* src =
            (const float4*)enc + ((size_t)(bx * 2048 + row)) * 64 + ck * 2;
        float4 v0 = src[0], v1 = src[1];
        __half2 h0 = __floats2half2_rn(v0.x, v0.y);
        __half2 h1 = __floats2half2_rn(v0.z, v0.w);
        __half2 h2 = __floats2half2_rn(v1.x, v1.y);
        __half2 h3 = __floats2half2_rn(v1.z, v1.w);
        uint4 h = make_uint4(*(uint32_t*)&h0, *(uint32_t*)&h1,
                             *(uint32_t*)&h2, *(uint32_t*)&h3);
        uint32_t sw = row * 512 + (((ck ^ (row & 7)) & 31) << 4);
        *(uint4*)(dyn + OFF_A + sw) = h;
    }
    // ---- load + split B: W rows by*32..+31 -> Bh + Bl fp16
    #pragma unroll
    for (int it = 0; it < 2; ++it) {
        const int g   = tid + it * 512;      // 0..1023
        const int row = g >> 5;              // 0..31
        const int ck  = g & 31;
        const float4* src =
            (const float4*)W + ((size_t)(by * 32 + row)) * 64 + ck * 2;
        float4 v0 = src[0], v1 = src[1];
        float vs[8] = {v0.x, v0.y, v0.z, v0.w, v1.x, v1.y, v1.z, v1.w};
        uint4 h, l;
        uint32_t* hp = (uint32_t*)&h;
        uint32_t* lp = (uint32_t*)&l;
        #pragma unroll
        for (int j = 0; j < 4; ++j) {
            __half2 hh = __floats2half2_rn(vs[j * 2], vs[j * 2 + 1]);
            float rx = vs[j * 2]     - __half2float(__low2half(hh));
            float ry = vs[j * 2 + 1] - __half2float(__high2half(hh));
            __half2 ll = __floats2half2_rn(rx, ry);
            hp[j] = *(uint32_t*)&hh;
            lp[j] = *(uint32_t*)&ll;
        }
        uint32_t sw = row * 512 + (((ck ^ (row & 7)) & 31) << 4);
        *(uint4*)(dyn + OFF_BH + sw) = h;
        *(uint4*)(dyn + OFF_BL + sw) = l;
    }
    __syncthreads();

    // ---- warp tiling: 16 warps = 2(Kq) x 4(M: 32 rows) x 2(N: 16 cols)
    const int kq = wid >> 3;         // K half: 0 -> k 0..127, 1 -> 128..255
    const int wm = (wid >> 1) & 3;
    const int wn = wid & 1;
    const int rl = lid & 15;
    const int kadd = lid >> 4;

    const int aRow0 = wm * 32 + rl;
    const int aRow1 = aRow0 + 16;
    const uint32_t aOff0 = aRow0 * 512;
    const uint32_t aOff1 = aRow1 * 512;
    const int ax0 = aRow0 & 7, ax1 = aRow1 & 7;
    const int bRow = wn * 16 + rl;
    const uint32_t bOff = bRow * 512;
    const int bx8 = bRow & 7;

    float acc[2][2][4];
    #pragma unroll
    for (int i = 0; i < 2; ++i)
        #pragma unroll
        for (int j = 0; j < 2; ++j)
            #pragma unroll
            for (int q = 0; q < 4; ++q)
                acc[i][j][q] = 0.f;

    // ---- mainloop: 8 k16 iters (this warp's K half); 4 ldmx4 + 8 HMMA each
    #pragma unroll
    for (int i = 0; i < 8; ++i) {
        const int ch = (kq * 8 + i) * 2 + kadd;
        uint32_t a0[4], a1[4], bh[4], bl[4];
        ldmx4(a0, sbase + OFF_A  + aOff0 + (((ch ^ ax0) & 31) << 4));
        ldmx4(a1, sbase + OFF_A  + aOff1 + (((ch ^ ax1) & 31) << 4));
        ldmx4(bh, sbase + OFF_BH + bOff  + (((ch ^ bx8) & 31) << 4));
        ldmx4(bl, sbase + OFF_BL + bOff  + (((ch ^ bx8) & 31) << 4));
        mma16816(acc[0][0], a0, bh[0], bh[2]);
        mma16816(acc[0][1], a0, bh[1], bh[3]);
        mma16816(acc[1][0], a1, bh[0], bh[2]);
        mma16816(acc[1][1], a1, bh[1], bh[3]);
        mma16816(acc[0][0], a0, bl[0], bl[2]);
        mma16816(acc[0][1], a0, bl[1], bl[3]);
        mma16816(acc[1][0], a1, bl[0], bl[2]);
        mma16816(acc[1][1], a1, bl[1], bl[3]);
    }

    // ---- K-split reduction via smem (reuse A region; tiles no longer read)
    __syncthreads();
    const int qr = lid >> 2;         // 0..7
    const int qc = (lid & 3) * 2;    // 0,2,4,6
    const int pos = wm * 2 + wn;     // tile position 0..7

    if (kq == 1) {
        #pragma unroll
        for (int mt = 0; mt < 2; ++mt)
            #pragma unroll
            for (int h = 0; h < 2; ++h)
                #pragma unroll
                for (int nt = 0; nt < 2; ++nt) {
                    int row = mt * 16 + h * 8 + qr;       // 0..31
                    int col = nt * 8 + qc;                // 0..7 (pairs)
                    float2 v = make_float2(acc[mt][nt][h * 2 + 0],
                                           acc[mt][nt][h * 2 + 1]);
                    *(float2*)(dyn + pos * 2048 + row * 64 + col * 4) = v;
                }
    }
    __syncthreads();

    if (kq == 0) {
        #pragma unroll
        for (int mt = 0; mt < 2; ++mt) {
            #pragma unroll
            for (int h = 0; h < 2; ++h) {
                const int mrow = mt * 16 + h * 8 + qr;    // 0..31 local
                const int m = wm * 32 + mrow;             // 0..127
                const int n = m & 3, ls = m >> 2;
                const float scale = (n == 0) ? 1.0f
                                  : (n == 1) ? ((ls < 16) ? 0.1f : 1.0f)
                                  : 0.1f;
                float* orow = out + ((size_t)(bx * 128 + m)) * 256
                                  + by * 32 + wn * 16 + qc;
                const float* brow = bias + by * 32 + wn * 16 + qc;
                #pragma unroll
                for (int nt = 0; nt < 2; ++nt) {
                    float2 part = *(const float2*)(dyn + pos * 2048
                                       + mrow * 64 + (nt * 8 + qc) * 4);
                    float2 bb = *(const float2*)(brow + nt * 8);
                    float2 o;
                    o.x = tanh_fast(fmaf(scale,
                              acc[mt][nt][h * 2 + 0] + part.x, bb.x));
                    o.y = tanh_fast(fmaf(scale,
                              acc[mt][nt][h * 2 + 1] + part.y, bb.y));
                    *(float2*)(orow + nt * 8) = o;
                }
            }
        }
    }
}

extern "C" void kernel_launch(void* const* d_in, const int* in_sizes, int n_in,
                              void* d_out, int out_size) {
    const float* enc  = (const float*)d_in[0];
    const float* W    = (const float*)d_in[1];
    const float* bias = (const float*)d_in[2];
    float* out = (float*)d_out;

    cudaFuncSetAttribute(spectral_hmma_kernel,
                         cudaFuncAttributeMaxDynamicSharedMemorySize, DYN_SMEM);
    dim3 grid(32, 8);
    spectral_hmma_kernel<<<grid, THREADS, DYN_SMEM>>>(enc, W, bias, out);
}

// round 11
// speedup vs baseline: 1.5970x; 1.2149x over previous
#include <cuda_runtime.h>
#include <cuda_fp16.h>
#include <stdint.h>

// out[r,o] = tanh(scale(r) * dot(enc_row(r), W[o,:]) + b[o])
//   r = b*128 + m (m = l*4+n, l<32) -> M=4096 ; enc phys row = b*2048 + m
//   K=256, N=256. (Spectral DCT/mask/IDCT collapses to mask*enc since the
//   band mask is independent of the DCT index.)
//
// fp16 HMMA m16n8k16: A single fp16 (err 2^-12), B split hi+lo:
// D = A*Bh + A*Bl, fp32 accum -> rel err ~2.2e-4 (measured R10).
//
// Round 11: K-chunked register-staged software pipeline (4 chunks of 64):
// LDGs for chunk c+1 issue before MMA of chunk c -> load latency hidden;
// each chunk fills distinct smem columns (no double buffer), 1 sync/chunk.
// 256 threads, warp tile 32x32 (4Mx2N warps): 6 ldmx4 + 16 HMMA per k16,
// CTA LDSM traffic ~393KB (half of R9/R10). smem 128KB, grid (32,4)=1 wave.

#define THREADS 256
#define OFF_A  0
#define OFF_BH 65536
#define OFF_BL 98304
#define DYN_SMEM 131072

static __device__ __forceinline__ uint32_t smem_u32(const void* p) {
    uint32_t a;
    asm("{ .reg .u64 t; cvta.to.shared.u64 t, %1; cvt.u32.u64 %0, t; }"
        : "=r"(a) : "l"(p));
    return a;
}

static __device__ __forceinline__ void ldmx4(uint32_t* r, uint32_t addr) {
    asm volatile("ldmatrix.sync.aligned.m8n8.x4.shared.b16 {%0,%1,%2,%3}, [%4];"
                 : "=r"(r[0]), "=r"(r[1]), "=r"(r[2]), "=r"(r[3]) : "r"(addr));
}

static __device__ __forceinline__ void mma16816(float* c, const uint32_t* a,
                                                uint32_t b0, uint32_t b1) {
    asm volatile(
        "mma.sync.aligned.m16n8k16.row.col.f32.f16.f16.f32 "
        "{%0,%1,%2,%3},{%4,%5,%6,%7},{%8,%9},{%0,%1,%2,%3};"
        : "+f"(c[0]), "+f"(c[1]), "+f"(c[2]), "+f"(c[3])
        : "r"(a[0]), "r"(a[1]), "r"(a[2]), "r"(a[3]), "r"(b0), "r"(b1));
}

static __device__ __forceinline__ float tanh_fast(float x) {
    float e = __expf(2.0f * x);
    return 1.0f - __fdividef(2.0f, e + 1.0f);
}

static __device__ __forceinline__ uint4 cvt8_h(const float4& v0, const float4& v1) {
    __half2 h0 = __floats2half2_rn(v0.x, v0.y);
    __half2 h1 = __floats2half2_rn(v0.z, v0.w);
    __half2 h2 = __floats2half2_rn(v1.x, v1.y);
    __half2 h3 = __floats2half2_rn(v1.z, v1.w);
    return make_uint4(*(uint32_t*)&h0, *(uint32_t*)&h1,
                      *(uint32_t*)&h2, *(uint32_t*)&h3);
}

__global__ __launch_bounds__(THREADS, 1) void spectral_hmma_kernel(
    const float* __restrict__ enc,
    const float* __restrict__ W,
    const float* __restrict__ bias,
    float* __restrict__ out)
{
    extern __shared__ __align__(16) uint8_t dyn[];
    const uint32_t sbase = smem_u32(dyn);

    const int tid = threadIdx.x;
    const int wid = tid >> 5;
    const int lid = tid & 31;
    const int bx = blockIdx.x;   // batch (M=128 rows), 0..31
    const int by = blockIdx.y;   // N tile (64 cols), 0..3

    const float4* __restrict__ encv = (const float4*)enc;
    const float4* __restrict__ Wv   = (const float4*)W;

    // per-thread chunk-load geometry (fixed across chunks)
    int aRowL[4], aCkl[4];
    #pragma unroll
    for (int s = 0; s < 4; ++s) {
        int g = tid + s * 256;          // 0..1023
        aRowL[s] = g >> 3;              // 0..127
        aCkl[s]  = g & 7;               // local 16B-chunk within k64
    }
    int bRowL[2], bCkl[2];
    #pragma unroll
    for (int s = 0; s < 2; ++s) {
        int g = tid + s * 256;          // 0..511
        bRowL[s] = g >> 3;              // 0..63
        bCkl[s]  = g & 7;
    }

    float4 sa[4][2], sb[2][2];

    // ---- prefetch chunk c into registers
    auto prefetch = [&](int c) {
        #pragma unroll
        for (int s = 0; s < 4; ++s) {
            const float4* p = encv
                + ((size_t)(bx * 2048 + aRowL[s])) * 64 + (c * 8 + aCkl[s]) * 2;
            sa[s][0] = p[0]; sa[s][1] = p[1];
        }
        #pragma unroll
        for (int s = 0; s < 2; ++s) {
            const float4* p = Wv
                + ((size_t)(by * 64 + bRowL[s])) * 64 + (c * 8 + bCkl[s]) * 2;
            sb[s][0] = p[0]; sb[s][1] = p[1];
        }
    };

    // ---- convert + store chunk c to smem
    auto commit = [&](int c) {
        #pragma unroll
        for (int s = 0; s < 4; ++s) {
            int row = aRowL[s], ck = c * 8 + aCkl[s];
            uint32_t sw = row * 512 + (((ck ^ (row & 7)) & 31) << 4);
            *(uint4*)(dyn + OFF_A + sw) = cvt8_h(sa[s][0], sa[s][1]);
        }
        #pragma unroll
        for (int s = 0; s < 2; ++s) {
            int row = bRowL[s], ck = c * 8 + bCkl[s];
            float vs[8] = {sb[s][0].x, sb[s][0].y, sb[s][0].z, sb[s][0].w,
                           sb[s][1].x, sb[s][1].y, sb[s][1].z, sb[s][1].w};
            uint4 h, l;
            uint32_t* hp = (uint32_t*)&h;
            uint32_t* lp = (uint32_t*)&l;
            #pragma unroll
            for (int j = 0; j < 4; ++j) {
                __half2 hh = __floats2half2_rn(vs[j * 2], vs[j * 2 + 1]);
                float rx = vs[j * 2]     - __half2float(__low2half(hh));
                float ry = vs[j * 2 + 1] - __half2float(__high2half(hh));
                __half2 ll = __floats2half2_rn(rx, ry);
                hp[j] = *(uint32_t*)&hh;
                lp[j] = *(uint32_t*)&ll;
            }
            uint32_t sw = row * 512 + (((ck ^ (row & 7)) & 31) << 4);
            *(uint4*)(dyn + OFF_BH + sw) = h;
            *(uint4*)(dyn + OFF_BL + sw) = l;
        }
    };

    // ---- warp tiling: 8 warps = 4(M: 32 rows) x 2(N: 32 cols)
    const int wm = wid >> 1;
    const int wn = wid & 1;
    const int rl = lid & 15;
    const int kadd = lid >> 4;

    const int aR0 = wm * 32 + rl, aR1 = aR0 + 16;
    const uint32_t aO0 = aR0 * 512, aO1 = aR1 * 512;
    const int ax0 = aR0 & 7, ax1 = aR1 & 7;
    const int bR0 = wn * 32 + rl, bR1 = bR0 + 16;
    const uint32_t bO0 = bR0 * 512, bO1 = bR1 * 512;
    const int bx0 = bR0 & 7, bx1 = bR1 & 7;

    float acc[2][4][4];
    #pragma unroll
    for (int i = 0; i < 2; ++i)
        #pragma unroll
        for (int j = 0; j < 4; ++j)
            #pragma unroll
            for (int q = 0; q < 4; ++q)
                acc[i][j][q] = 0.f;

    // ---- pipelined mainloop over 4 K-chunks
    prefetch(0);
    commit(0);
    __syncthreads();

    for (int c = 0; c < 4; ++c) {
        if (c < 3) prefetch(c + 1);   // LDGs in flight during this chunk's MMA

        #pragma unroll
        for (int i = 0; i < 4; ++i) {
            const int ch = (c * 4 + i) * 2 + kadd;
            uint32_t a0[4], a1[4], bh0[4], bh1[4], bl0[4], bl1[4];
            ldmx4(a0,  sbase + OFF_A  + aO0 + (((ch ^ ax0) & 31) << 4));
            ldmx4(a1,  sbase + OFF_A  + aO1 + (((ch ^ ax1) & 31) << 4));
            ldmx4(bh0, sbase + OFF_BH + bO0 + (((ch ^ bx0) & 31) << 4));
            ldmx4(bh1, sbase + OFF_BH + bO1 + (((ch ^ bx1) & 31) << 4));
            ldmx4(bl0, sbase + OFF_BL + bO0 + (((ch ^ bx0) & 31) << 4));
            ldmx4(bl1, sbase + OFF_BL + bO1 + (((ch ^ bx1) & 31) << 4));
            #pragma unroll
            for (int mt = 0; mt < 2; ++mt) {
                const uint32_t* a = mt ? a1 : a0;
                mma16816(acc[mt][0], a, bh0[0], bh0[2]);
                mma16816(acc[mt][1], a, bh0[1], bh0[3]);
                mma16816(acc[mt][2], a, bh1[0], bh1[2]);
                mma16816(acc[mt][3], a, bh1[1], bh1[3]);
                mma16816(acc[mt][0], a, bl0[0], bl0[2]);
                mma16816(acc[mt][1], a, bl0[1], bl0[3]);
                mma16816(acc[mt][2], a, bl1[0], bl1[2]);
                mma16816(acc[mt][3], a, bl1[1], bl1[3]);
            }
        }

        if (c < 3) {
            commit(c + 1);
            __syncthreads();
        }
    }

    // ---- epilogue: band scale, bias, tanh, store
    const int qr = lid >> 2;
    const int qc = (lid & 3) * 2;
    #pragma unroll
    for (int mt = 0; mt < 2; ++mt) {
        #pragma unroll
        for (int h = 0; h < 2; ++h) {
            const int m = wm * 32 + mt * 16 + h * 8 + qr;   // 0..127
            const int n = m & 3, ls = m >> 2;
            const float scale = (n == 0) ? 1.0f
                              : (n == 1) ? ((ls < 16) ? 0.1f : 1.0f)
                              : 0.1f;
            float* orow = out + ((size_t)(bx * 128 + m)) * 256
                              + by * 64 + wn * 32 + qc;
            const float* brow = bias + by * 64 + wn * 32 + qc;
            #pragma unroll
            for (int nt = 0; nt < 4; ++nt) {
                float2 bb = *(const float2*)(brow + nt * 8);
                float2 o;
                o.x = tanh_fast(fmaf(scale, acc[mt][nt][h * 2 + 0], bb.x));
                o.y = tanh_fast(fmaf(scale, acc[mt][nt][h * 2 + 1], bb.y));
                *(float2*)(orow + nt * 8) = o;
            }
        }
    }
}

extern "C" void kernel_launch(void* const* d_in, const int* in_sizes, int n_in,
                              void* d_out, int out_size) {
    const float* enc  = (const float*)d_in[0];
    const float* W    = (const float*)d_in[1];
    const float* bias = (const float*)d_in[2];
    float* out = (float*)d_out;

    cudaFuncSetAttribute(spectral_hmma_kernel,
                         cudaFuncAttributeMaxDynamicSharedMemorySize, DYN_SMEM);
    dim3 grid(32, 4);
    spectral_hmma_kernel<<<grid, THREADS, DYN_SMEM>>>(enc, W, bias, out);
}